// round 13
// baseline (speedup 1.0000x reference)
#include <cuda_runtime.h>
#include <cuda_bf16.h>
#include <cstdint>

#define NE 1000000
#define NN 500000
#define NT 600000

// Scratch (device globals — no cudaMalloc allowed). 16B-aligned for float4/red.v4.
__device__ __align__(16) float g_y[(size_t)NN * 64];   // node accum, then ytilde = y@w0 in-place
__device__ __align__(16) float g_z1[(size_t)NE * 64];  // z1 accumulator
__device__ int g_en[(size_t)NE * 2];                   // normalized int32 edge_nodes
__device__ int g_te[(size_t)NT * 3];                   // normalized int32 tri_edges

// Vectorized fp32 reduction (no return) — 1 L2 atomic op per 16B (sm_90+)
__device__ __forceinline__ void red_add_v4(float* a, float x, float y, float z, float w) {
    asm volatile("red.global.add.v4.f32 [%0], {%1,%2,%3,%4};"
                 :: "l"(a), "f"(x), "f"(y), "f"(z), "f"(w) : "memory");
}

// ---------------- tensor-core bf16x2-split GEMM machinery ----------------
// Shared tile: A split into hi/lo bf16 (stride 72 = 144B rows, conflict-free
// for ldmatrix), W split likewise. After the MMA loop the W region is reused
// as the fp32 C staging buffer (stride 68).
struct __align__(16) SmemGemm {
    unsigned short Ah[64 * 72];
    unsigned short Al[64 * 72];
    unsigned short W[2][64 * 72];  // [0]=hi, [1]=lo; reused as float stage[64*68]
};

__device__ __forceinline__ unsigned int saddr(const void* p) {
    return (unsigned int)__cvta_generic_to_shared(p);
}
__device__ __forceinline__ void ldsm4(unsigned int r[4], unsigned int a) {
    asm volatile("ldmatrix.sync.aligned.m8n8.x4.shared.b16 {%0,%1,%2,%3}, [%4];"
                 : "=r"(r[0]), "=r"(r[1]), "=r"(r[2]), "=r"(r[3]) : "r"(a));
}
__device__ __forceinline__ void ldsm4t(unsigned int r[4], unsigned int a) {
    asm volatile("ldmatrix.sync.aligned.m8n8.x4.trans.shared.b16 {%0,%1,%2,%3}, [%4];"
                 : "=r"(r[0]), "=r"(r[1]), "=r"(r[2]), "=r"(r[3]) : "r"(a));
}
__device__ __forceinline__ void mma_bf16(float c[4], const unsigned int a[4],
                                         unsigned int b0, unsigned int b1) {
    asm volatile(
        "mma.sync.aligned.m16n8k16.row.col.f32.bf16.bf16.f32 "
        "{%0,%1,%2,%3}, {%4,%5,%6,%7}, {%8,%9}, {%0,%1,%2,%3};"
        : "+f"(c[0]), "+f"(c[1]), "+f"(c[2]), "+f"(c[3])
        : "r"(a[0]), "r"(a[1]), "r"(a[2]), "r"(a[3]), "r"(b0), "r"(b1));
}
__device__ __forceinline__ void split2(float v, unsigned short* hp, unsigned short* lp) {
    __nv_bfloat16 h = __float2bfloat16_rn(v);
    __nv_bfloat16 l = __float2bfloat16_rn(v - __bfloat162float(h));
    *hp = *(unsigned short*)&h;
    *lp = *(unsigned short*)&l;
}

// Load W (64x64 row-major fp32) into split shared tiles.
__device__ __forceinline__ void fill_w(SmemGemm* s, const float* __restrict__ w, int tid) {
    for (int i = tid; i < 4096; i += 256) {
        int k = i >> 6, c = i & 63;
        split2(w[i], &s->W[0][k * 72 + c], &s->W[1][k * 72 + c]);
    }
}

// 64x64x64 GEMM on tensor cores; 8 warps = 4 m-tiles x 2 n-halves.
// acc[j] is the m16n8 fragment for n = warp_n + 8j. Then stage C to shared.
__device__ __forceinline__ void mma_core_and_stage(SmemGemm* s, int tid, float* stage) {
    int lane = tid & 31, wid = tid >> 5;
    int warp_m = (wid & 3) * 16;
    int warp_n = (wid >> 2) * 32;
    int r8 = (lane & 7) + ((lane >> 3) & 1) * 8;  // ldmatrix row-within-16
    int c8 = (lane >> 4) * 8;                      // ldmatrix col-half
    float acc[4][4] = {};
#pragma unroll
    for (int k0 = 0; k0 < 64; k0 += 16) {
        unsigned int ah[4], al[4], bh[2][4], bl[2][4];
        ldsm4(ah, saddr(&s->Ah[(warp_m + r8) * 72 + k0 + c8]));
        ldsm4(al, saddr(&s->Al[(warp_m + r8) * 72 + k0 + c8]));
        ldsm4t(bh[0], saddr(&s->W[0][(k0 + r8) * 72 + warp_n + c8]));
        ldsm4t(bh[1], saddr(&s->W[0][(k0 + r8) * 72 + warp_n + 16 + c8]));
        ldsm4t(bl[0], saddr(&s->W[1][(k0 + r8) * 72 + warp_n + c8]));
        ldsm4t(bl[1], saddr(&s->W[1][(k0 + r8) * 72 + warp_n + 16 + c8]));
#pragma unroll
        for (int j = 0; j < 4; j++) {
            int g = j >> 1, p = 2 * (j & 1);
            mma_bf16(acc[j], ah, bh[g][p], bh[g][p + 1]);  // hi*hi
            mma_bf16(acc[j], ah, bl[g][p], bl[g][p + 1]);  // hi*lo
            mma_bf16(acc[j], al, bh[g][p], bh[g][p + 1]);  // lo*hi
        }
    }
    __syncthreads();  // all ldmatrix reads of W done before stage overwrites it
    int gid = lane >> 2, tig = lane & 3;
#pragma unroll
    for (int j = 0; j < 4; j++) {
        int n = warp_n + 8 * j + 2 * tig;
        *(float2*)&stage[(warp_m + gid) * 68 + n]     = make_float2(acc[j][0], acc[j][1]);
        *(float2*)&stage[(warp_m + gid + 8) * 68 + n] = make_float2(acc[j][2], acc[j][3]);
    }
    __syncthreads();
}

// K0: normalize indices to int32, auto-detecting int64 vs int32 source.
__global__ void __launch_bounds__(256) k_conv(const int* __restrict__ raw,
                                              int* __restrict__ dst, int n) {
    __shared__ int is64;
    if (threadIdx.x == 0) {
        int z = 1;
        for (int k = 1; k < 128; k += 2) z &= (raw[k] == 0);
        is64 = z;
    }
    __syncthreads();
    int i = blockIdx.x * 256 + threadIdx.x;
    if (i < n) dst[i] = is64 ? raw[2 * i] : raw[i];
}

// K1: scatter +-x rows into node accumulator y. 16 threads (float4 lanes) per edge.
__global__ void __launch_bounds__(256) k_node_scatter(const float4* __restrict__ x4) {
    long long tid = (long long)blockIdx.x * 256 + threadIdx.x;
    if (tid >= (long long)NE * 16) return;
    int e = (int)(tid >> 4), q = (int)(tid & 15);
    float4 v = x4[(size_t)e * 16 + q];
    int t = g_en[2 * (size_t)e];
    int h = g_en[2 * (size_t)e + 1];
    red_add_v4(g_y + (size_t)t * 64 + q * 4, -v.x, -v.y, -v.z, -v.w);
    red_add_v4(g_y + (size_t)h * 64 + q * 4,  v.x,  v.y,  v.z,  v.w);
}

// K2: ytilde = y @ w0, in place (64 block-private rows per block).
__global__ void __launch_bounds__(256) k_node_gemm(const float* __restrict__ w0) {
    __shared__ SmemGemm s;
    int tid = threadIdx.x;
    size_t row0 = (size_t)blockIdx.x * 64;
    fill_w(&s, w0, tid);
    for (int i = tid; i < 4096; i += 256) {
        int r = i >> 6, c = i & 63;
        float v = (row0 + r < NN) ? g_y[(row0 + r) * 64 + c] : 0.f;
        split2(v, &s.Ah[r * 72 + c], &s.Al[r * 72 + c]);
    }
    __syncthreads();
    float* stage = (float*)s.W;
    mma_core_and_stage(&s, tid, stage);
    for (int i = tid; i < 1024; i += 256) {
        int r = i >> 4, q = i & 15;
        if (row0 + r < NN)
            *(float4*)&g_y[(row0 + r) * 64 + q * 4] = *(const float4*)&stage[r * 68 + q * 4];
    }
}

// K3: per triangle: w = x[e0]-x[e1]+x[e2]; p = w@w2; scatter +p,-p,+p into z1.
__global__ void __launch_bounds__(256) k_tri(const float4* __restrict__ x4,
                                             const float* __restrict__ w2) {
    __shared__ SmemGemm s;
    __shared__ int se[192];
    int tid = threadIdx.x;
    size_t t0 = (size_t)blockIdx.x * 64;
    fill_w(&s, w2, tid);
    if (tid < 192) se[tid] = g_te[t0 * 3 + tid];
    __syncthreads();
    for (int i = tid; i < 1024; i += 256) {
        int r = i >> 4, q = i & 15;
        int e0 = se[r * 3], e1 = se[r * 3 + 1], e2 = se[r * 3 + 2];
        float4 a = x4[(size_t)e0 * 16 + q];
        float4 b = x4[(size_t)e1 * 16 + q];
        float4 c = x4[(size_t)e2 * 16 + q];
        float d[4] = {a.x - b.x + c.x, a.y - b.y + c.y, a.z - b.z + c.z, a.w - b.w + c.w};
#pragma unroll
        for (int t = 0; t < 4; t++)
            split2(d[t], &s.Ah[r * 72 + q * 4 + t], &s.Al[r * 72 + q * 4 + t]);
    }
    __syncthreads();
    float* stage = (float*)s.W;
    mma_core_and_stage(&s, tid, stage);
    for (int i = tid; i < 1024; i += 256) {
        int r = i >> 4, q = i & 15;
        float4 p = *(const float4*)&stage[r * 68 + q * 4];
        int e0 = se[r * 3], e1 = se[r * 3 + 1], e2 = se[r * 3 + 2];
        red_add_v4(g_z1 + (size_t)e0 * 64 + q * 4,  p.x,  p.y,  p.z,  p.w);
        red_add_v4(g_z1 + (size_t)e1 * 64 + q * 4, -p.x, -p.y, -p.z, -p.w);
        red_add_v4(g_z1 + (size_t)e2 * 64 + q * 4,  p.x,  p.y,  p.z,  p.w);
    }
}

// K4: out = tanh(x@w1 + z1 + ytilde[head] - ytilde[tail]).
__global__ void __launch_bounds__(256) k_final(const float4* __restrict__ x4,
                                               const float* __restrict__ w1,
                                               float* __restrict__ out) {
    __shared__ SmemGemm s;
    int tid = threadIdx.x;
    size_t r0 = (size_t)blockIdx.x * 64;
    fill_w(&s, w1, tid);
    {
        const float* xf = (const float*)x4;
        for (int i = tid; i < 4096; i += 256) {
            int r = i >> 6, c = i & 63;
            split2(xf[(r0 + r) * 64 + c], &s.Ah[r * 72 + c], &s.Al[r * 72 + c]);
        }
    }
    __syncthreads();
    float* stage = (float*)s.W;
    mma_core_and_stage(&s, tid, stage);
    for (int i = tid; i < 1024; i += 256) {
        int r = i >> 4, q = i & 15;
        size_t row = r0 + r;
        int t = g_en[2 * row];
        int h = g_en[2 * row + 1];
        float4 g = *(const float4*)&stage[r * 68 + q * 4];
        const float4 z1v = *(const float4*)&g_z1[row * 64 + q * 4];
        const float4 yh  = *(const float4*)&g_y[(size_t)h * 64 + q * 4];
        const float4 yt  = *(const float4*)&g_y[(size_t)t * 64 + q * 4];
        float4 o;
        o.x = tanhf(g.x + z1v.x + yh.x - yt.x);
        o.y = tanhf(g.y + z1v.y + yh.y - yt.y);
        o.z = tanhf(g.z + z1v.z + yh.z - yt.z);
        o.w = tanhf(g.w + z1v.w + yh.w - yt.w);
        *(float4*)&out[row * 64 + q * 4] = o;
    }
}

extern "C" void kernel_launch(void* const* d_in, const int* in_sizes, int n_in,
                              void* d_out, int out_size) {
    // Resolve inputs by element count:
    //   x: 64,000,000  edge_nodes: 2,000,000  tri_edges: 1,800,000  w: 4,096 (x3, in order)
    const float* x = nullptr;
    const int* en_raw = nullptr;
    const int* te_raw = nullptr;
    const float* w[3] = {nullptr, nullptr, nullptr};
    int wi = 0;
    for (int i = 0; i < n_in; i++) {
        switch (in_sizes[i]) {
            case 64000000: x = (const float*)d_in[i]; break;
            case 2000000:  en_raw = (const int*)d_in[i]; break;
            case 1800000:  te_raw = (const int*)d_in[i]; break;
            case 4096:     if (wi < 3) w[wi++] = (const float*)d_in[i]; break;
            default: break;
        }
    }
    const float* w0 = w[0];
    const float* w1 = w[1];
    const float* w2 = w[2];
    float* out = (float*)d_out;

    void *py = nullptr, *pz = nullptr, *pen = nullptr, *pte = nullptr;
    cudaGetSymbolAddress(&py, g_y);
    cudaGetSymbolAddress(&pz, g_z1);
    cudaGetSymbolAddress(&pen, g_en);
    cudaGetSymbolAddress(&pte, g_te);

    // Fork/join streams (created on first, non-captured call).
    static cudaStream_t sA = nullptr, sB = nullptr;
    static cudaEvent_t evRoot = nullptr, evA = nullptr, evB = nullptr;
    if (sA == nullptr) {
        cudaStreamCreateWithFlags(&sA, cudaStreamNonBlocking);
        cudaStreamCreateWithFlags(&sB, cudaStreamNonBlocking);
        cudaEventCreateWithFlags(&evRoot, cudaEventDisableTiming);
        cudaEventCreateWithFlags(&evA, cudaEventDisableTiming);
        cudaEventCreateWithFlags(&evB, cudaEventDisableTiming);
    }

    cudaEventRecord(evRoot, 0);
    cudaStreamWaitEvent(sA, evRoot, 0);
    cudaStreamWaitEvent(sB, evRoot, 0);

    // Branch A — node pipeline: memset y -> conv en -> scatter -> y@w0.
    cudaMemsetAsync(py, 0, (size_t)NN * 64 * sizeof(float), sA);
    k_conv<<<(NE * 2 + 255) / 256, 256, 0, sA>>>(en_raw, (int*)pen, NE * 2);
    k_node_scatter<<<(NE * 16 + 255) / 256, 256, 0, sA>>>((const float4*)x);
    k_node_gemm<<<(NN + 63) / 64, 256, 0, sA>>>(w0);
    cudaEventRecord(evA, sA);

    // Branch B — triangle pipeline: memset z1 -> conv te -> tri GEMM + scatter.
    cudaMemsetAsync(pz, 0, (size_t)NE * 64 * sizeof(float), sB);
    k_conv<<<(NT * 3 + 255) / 256, 256, 0, sB>>>(te_raw, (int*)pte, NT * 3);
    k_tri<<<NT / 64, 256, 0, sB>>>((const float4*)x, w2);
    cudaEventRecord(evB, sB);

    // Join, then fused final GEMM + epilogue.
    cudaStreamWaitEvent(0, evA, 0);
    cudaStreamWaitEvent(0, evB, 0);
    k_final<<<NE / 64, 256>>>((const float4*)x, w1, out);
}

// round 14
// speedup vs baseline: 1.3884x; 1.3884x over previous
#include <cuda_runtime.h>
#include <cuda_bf16.h>
#include <cstdint>

#define NE 1000000
#define NN 500000
#define NT 600000

// Scratch (device globals — no cudaMalloc allowed). 16B-aligned for float4/red.v4.
__device__ __align__(16) float g_y[(size_t)NN * 64];   // node accum, then ytilde = y@w0 in-place
__device__ __align__(16) float g_z1[(size_t)NE * 64];  // z1 accumulator
// Pre-split weights in ldmatrix-ready layout (stride 72 ushorts/row): [w_id][hi/lo]
__device__ __align__(16) unsigned short g_wsplit[3][2][64 * 72];

// Vectorized fp32 reduction (no return) — 1 L2 atomic op per 16B (sm_90+)
__device__ __forceinline__ void red_add_v4(float* a, float x, float y, float z, float w) {
    asm volatile("red.global.add.v4.f32 [%0], {%1,%2,%3,%4};"
                 :: "l"(a), "f"(x), "f"(y), "f"(z), "f"(w) : "memory");
}

// int64-vs-int32 detection on raw index buffer: int64 (values < 2^31) has all
// odd 32-bit words zero; random int32 indices make 4 zero odd-words ~(1e-6)^4.
__device__ __forceinline__ int detect64(const int* __restrict__ raw) {
    return (raw[1] == 0) & (raw[3] == 0) & (raw[5] == 0) & (raw[7] == 0);
}

// ---------------- tensor-core bf16x2-split GEMM machinery ----------------
struct __align__(16) SmemGemm {
    unsigned short Ah[64 * 72];
    unsigned short Al[64 * 72];
    unsigned short W[2][64 * 72];  // [0]=hi, [1]=lo; reused as float stage[64*68]
};

__device__ __forceinline__ unsigned int saddr(const void* p) {
    return (unsigned int)__cvta_generic_to_shared(p);
}
__device__ __forceinline__ void ldsm4(unsigned int r[4], unsigned int a) {
    asm volatile("ldmatrix.sync.aligned.m8n8.x4.shared.b16 {%0,%1,%2,%3}, [%4];"
                 : "=r"(r[0]), "=r"(r[1]), "=r"(r[2]), "=r"(r[3]) : "r"(a));
}
__device__ __forceinline__ void ldsm4t(unsigned int r[4], unsigned int a) {
    asm volatile("ldmatrix.sync.aligned.m8n8.x4.trans.shared.b16 {%0,%1,%2,%3}, [%4];"
                 : "=r"(r[0]), "=r"(r[1]), "=r"(r[2]), "=r"(r[3]) : "r"(a));
}
__device__ __forceinline__ void mma_bf16(float c[4], const unsigned int a[4],
                                         unsigned int b0, unsigned int b1) {
    asm volatile(
        "mma.sync.aligned.m16n8k16.row.col.f32.bf16.bf16.f32 "
        "{%0,%1,%2,%3}, {%4,%5,%6,%7}, {%8,%9}, {%0,%1,%2,%3};"
        : "+f"(c[0]), "+f"(c[1]), "+f"(c[2]), "+f"(c[3])
        : "r"(a[0]), "r"(a[1]), "r"(a[2]), "r"(a[3]), "r"(b0), "r"(b1));
}

// Pack an fp32 pair into bf16x2 hi + exact-residual bf16x2 lo (one cvt each).
__device__ __forceinline__ void pack_pair(float vx, float vy,
                                          unsigned short* hp, unsigned short* lp) {
    unsigned int h, l;
    asm("cvt.rn.bf16x2.f32 %0, %1, %2;" : "=r"(h) : "f"(vy), "f"(vx));
    float hx = __uint_as_float(h << 16);
    float hy = __uint_as_float(h & 0xFFFF0000u);
    asm("cvt.rn.bf16x2.f32 %0, %1, %2;" : "=r"(l) : "f"(vy - hy), "f"(vx - hx));
    *(unsigned int*)hp = h;
    *(unsigned int*)lp = l;
}

// Copy pre-split W (hi+lo, 9216B each) into shared with float4 loads.
__device__ __forceinline__ void copy_w(SmemGemm* s, int w_id, int tid) {
    const float4* sh = (const float4*)g_wsplit[w_id][0];
    const float4* sl = (const float4*)g_wsplit[w_id][1];
#pragma unroll
    for (int i = tid; i < 576; i += 256) {
        ((float4*)s->W[0])[i] = sh[i];
        ((float4*)s->W[1])[i] = sl[i];
    }
}

// 64x64x64 GEMM on tensor cores; 8 warps = 4 m-tiles x 2 n-halves.
// acc[j] is the m16n8 fragment for n = warp_n + 8j. Then stage C to shared.
__device__ __forceinline__ void mma_core_and_stage(SmemGemm* s, int tid, float* stage) {
    int lane = tid & 31, wid = tid >> 5;
    int warp_m = (wid & 3) * 16;
    int warp_n = (wid >> 2) * 32;
    int r8 = (lane & 7) + ((lane >> 3) & 1) * 8;  // ldmatrix row-within-16
    int c8 = (lane >> 4) * 8;                      // ldmatrix col-half
    float acc[4][4] = {};
#pragma unroll
    for (int k0 = 0; k0 < 64; k0 += 16) {
        unsigned int ah[4], al[4], bh[2][4], bl[2][4];
        ldsm4(ah, saddr(&s->Ah[(warp_m + r8) * 72 + k0 + c8]));
        ldsm4(al, saddr(&s->Al[(warp_m + r8) * 72 + k0 + c8]));
        ldsm4t(bh[0], saddr(&s->W[0][(k0 + r8) * 72 + warp_n + c8]));
        ldsm4t(bh[1], saddr(&s->W[0][(k0 + r8) * 72 + warp_n + 16 + c8]));
        ldsm4t(bl[0], saddr(&s->W[1][(k0 + r8) * 72 + warp_n + c8]));
        ldsm4t(bl[1], saddr(&s->W[1][(k0 + r8) * 72 + warp_n + 16 + c8]));
#pragma unroll
        for (int j = 0; j < 4; j++) {
            int g = j >> 1, p = 2 * (j & 1);
            mma_bf16(acc[j], ah, bh[g][p], bh[g][p + 1]);  // hi*hi
            mma_bf16(acc[j], ah, bl[g][p], bl[g][p + 1]);  // hi*lo
            mma_bf16(acc[j], al, bh[g][p], bh[g][p + 1]);  // lo*hi
        }
    }
    __syncthreads();  // all ldmatrix reads of W done before stage overwrites it
    int gid = lane >> 2, tig = lane & 3;
#pragma unroll
    for (int j = 0; j < 4; j++) {
        int n = warp_n + 8 * j + 2 * tig;
        *(float2*)&stage[(warp_m + gid) * 68 + n]     = make_float2(acc[j][0], acc[j][1]);
        *(float2*)&stage[(warp_m + gid + 8) * 68 + n] = make_float2(acc[j][2], acc[j][3]);
    }
    __syncthreads();
}

// K_prep: split all three weights into hi/lo bf16 (ldmatrix layout), once.
__global__ void __launch_bounds__(256) k_prep(const float* __restrict__ w0,
                                              const float* __restrict__ w1,
                                              const float* __restrict__ w2) {
    int idx = blockIdx.x * 256 + threadIdx.x;  // one fp32 PAIR per thread
    if (idx >= 3 * 2048) return;
    int w_id = idx >> 11;
    int p = idx & 2047;
    int k = p >> 5, c = (p & 31) * 2;
    const float* w = (w_id == 0) ? w0 : (w_id == 1) ? w1 : w2;
    float2 v = *(const float2*)&w[k * 64 + c];
    pack_pair(v.x, v.y, &g_wsplit[w_id][0][k * 72 + c], &g_wsplit[w_id][1][k * 72 + c]);
}

// K1: scatter +-x rows into node accumulator y. 16 threads (float4 lanes) per edge.
__global__ void __launch_bounds__(256) k_node_scatter(const float4* __restrict__ x4,
                                                      const int* __restrict__ en_raw) {
    __shared__ int s64;
    if (threadIdx.x == 0) s64 = detect64(en_raw);
    __syncthreads();
    long long tid = (long long)blockIdx.x * 256 + threadIdx.x;
    if (tid >= (long long)NE * 16) return;
    int e = (int)(tid >> 4), q = (int)(tid & 15);
    float4 v = x4[(size_t)e * 16 + q];
    int t, h;
    if (s64) { t = en_raw[4 * (size_t)e];     h = en_raw[4 * (size_t)e + 2]; }
    else     { t = en_raw[2 * (size_t)e];     h = en_raw[2 * (size_t)e + 1]; }
    red_add_v4(g_y + (size_t)t * 64 + q * 4, -v.x, -v.y, -v.z, -v.w);
    red_add_v4(g_y + (size_t)h * 64 + q * 4,  v.x,  v.y,  v.z,  v.w);
}

// K2: ytilde = y @ w0, in place (64 block-private rows per block).
__global__ void __launch_bounds__(256) k_node_gemm() {
    __shared__ SmemGemm s;
    int tid = threadIdx.x;
    size_t row0 = (size_t)blockIdx.x * 64;
    copy_w(&s, 0, tid);
    for (int i = tid; i < 1024; i += 256) {
        int r = i >> 4, q = i & 15;
        float4 v = make_float4(0.f, 0.f, 0.f, 0.f);
        if (row0 + r < NN) v = *(const float4*)&g_y[(row0 + r) * 64 + q * 4];
        pack_pair(v.x, v.y, &s.Ah[r * 72 + q * 4],     &s.Al[r * 72 + q * 4]);
        pack_pair(v.z, v.w, &s.Ah[r * 72 + q * 4 + 2], &s.Al[r * 72 + q * 4 + 2]);
    }
    __syncthreads();
    float* stage = (float*)s.W;
    mma_core_and_stage(&s, tid, stage);
    for (int i = tid; i < 1024; i += 256) {
        int r = i >> 4, q = i & 15;
        if (row0 + r < NN)
            *(float4*)&g_y[(row0 + r) * 64 + q * 4] = *(const float4*)&stage[r * 68 + q * 4];
    }
}

// K3: per triangle: w = x[e0]-x[e1]+x[e2]; p = w@w2; scatter +p,-p,+p into z1.
__global__ void __launch_bounds__(256) k_tri(const float4* __restrict__ x4,
                                             const int* __restrict__ te_raw) {
    __shared__ SmemGemm s;
    __shared__ int se[192];
    int tid = threadIdx.x;
    size_t t0 = (size_t)blockIdx.x * 64;
    __shared__ int s64;
    if (tid == 0) s64 = detect64(te_raw);
    copy_w(&s, 2, tid);
    __syncthreads();
    if (tid < 192)
        se[tid] = s64 ? te_raw[2 * (t0 * 3 + tid)] : te_raw[t0 * 3 + tid];
    __syncthreads();
    for (int i = tid; i < 1024; i += 256) {
        int r = i >> 4, q = i & 15;
        int e0 = se[r * 3], e1 = se[r * 3 + 1], e2 = se[r * 3 + 2];
        float4 a = x4[(size_t)e0 * 16 + q];
        float4 b = x4[(size_t)e1 * 16 + q];
        float4 c = x4[(size_t)e2 * 16 + q];
        pack_pair(a.x - b.x + c.x, a.y - b.y + c.y,
                  &s.Ah[r * 72 + q * 4],     &s.Al[r * 72 + q * 4]);
        pack_pair(a.z - b.z + c.z, a.w - b.w + c.w,
                  &s.Ah[r * 72 + q * 4 + 2], &s.Al[r * 72 + q * 4 + 2]);
    }
    __syncthreads();
    float* stage = (float*)s.W;
    mma_core_and_stage(&s, tid, stage);
    for (int i = tid; i < 1024; i += 256) {
        int r = i >> 4, q = i & 15;
        float4 p = *(const float4*)&stage[r * 68 + q * 4];
        int e0 = se[r * 3], e1 = se[r * 3 + 1], e2 = se[r * 3 + 2];
        red_add_v4(g_z1 + (size_t)e0 * 64 + q * 4,  p.x,  p.y,  p.z,  p.w);
        red_add_v4(g_z1 + (size_t)e1 * 64 + q * 4, -p.x, -p.y, -p.z, -p.w);
        red_add_v4(g_z1 + (size_t)e2 * 64 + q * 4,  p.x,  p.y,  p.z,  p.w);
    }
}

// K4: out = tanh(x@w1 + z1 + ytilde[head] - ytilde[tail]).
__global__ void __launch_bounds__(256) k_final(const float4* __restrict__ x4,
                                               const int* __restrict__ en_raw,
                                               float* __restrict__ out) {
    __shared__ SmemGemm s;
    __shared__ int s64;
    int tid = threadIdx.x;
    size_t r0 = (size_t)blockIdx.x * 64;
    if (tid == 0) s64 = detect64(en_raw);
    copy_w(&s, 1, tid);
    for (int i = tid; i < 1024; i += 256) {
        int r = i >> 4, q = i & 15;
        float4 v = x4[(r0 + r) * 16 + q];
        pack_pair(v.x, v.y, &s.Ah[r * 72 + q * 4],     &s.Al[r * 72 + q * 4]);
        pack_pair(v.z, v.w, &s.Ah[r * 72 + q * 4 + 2], &s.Al[r * 72 + q * 4 + 2]);
    }
    __syncthreads();
    float* stage = (float*)s.W;
    mma_core_and_stage(&s, tid, stage);
    for (int i = tid; i < 1024; i += 256) {
        int r = i >> 4, q = i & 15;
        size_t row = r0 + r;
        int t, h;
        if (s64) { t = en_raw[4 * row];  h = en_raw[4 * row + 2]; }
        else     { t = en_raw[2 * row];  h = en_raw[2 * row + 1]; }
        float4 g = *(const float4*)&stage[r * 68 + q * 4];
        const float4 z1v = *(const float4*)&g_z1[row * 64 + q * 4];
        const float4 yh  = *(const float4*)&g_y[(size_t)h * 64 + q * 4];
        const float4 yt  = *(const float4*)&g_y[(size_t)t * 64 + q * 4];
        float4 o;
        o.x = tanhf(g.x + z1v.x + yh.x - yt.x);
        o.y = tanhf(g.y + z1v.y + yh.y - yt.y);
        o.z = tanhf(g.z + z1v.z + yh.z - yt.z);
        o.w = tanhf(g.w + z1v.w + yh.w - yt.w);
        *(float4*)&out[row * 64 + q * 4] = o;
    }
}

extern "C" void kernel_launch(void* const* d_in, const int* in_sizes, int n_in,
                              void* d_out, int out_size) {
    // Resolve inputs by element count:
    //   x: 64,000,000  edge_nodes: 2,000,000  tri_edges: 1,800,000  w: 4,096 (x3, in order)
    const float* x = nullptr;
    const int* en_raw = nullptr;
    const int* te_raw = nullptr;
    const float* w[3] = {nullptr, nullptr, nullptr};
    int wi = 0;
    for (int i = 0; i < n_in; i++) {
        switch (in_sizes[i]) {
            case 64000000: x = (const float*)d_in[i]; break;
            case 2000000:  en_raw = (const int*)d_in[i]; break;
            case 1800000:  te_raw = (const int*)d_in[i]; break;
            case 4096:     if (wi < 3) w[wi++] = (const float*)d_in[i]; break;
            default: break;
        }
    }
    float* out = (float*)d_out;

    void *py = nullptr, *pz = nullptr;
    cudaGetSymbolAddress(&py, g_y);
    cudaGetSymbolAddress(&pz, g_z1);

    // Fork/join streams (created on first, non-captured call).
    static cudaStream_t sA = nullptr, sB = nullptr;
    static cudaEvent_t evRoot = nullptr, evA = nullptr, evB = nullptr;
    if (sA == nullptr) {
        cudaStreamCreateWithFlags(&sA, cudaStreamNonBlocking);
        cudaStreamCreateWithFlags(&sB, cudaStreamNonBlocking);
        cudaEventCreateWithFlags(&evRoot, cudaEventDisableTiming);
        cudaEventCreateWithFlags(&evA, cudaEventDisableTiming);
        cudaEventCreateWithFlags(&evB, cudaEventDisableTiming);
    }

    // Weight split prep on the root stream, then fork.
    k_prep<<<24, 256>>>(w[0], w[1], w[2]);
    cudaEventRecord(evRoot, 0);
    cudaStreamWaitEvent(sA, evRoot, 0);
    cudaStreamWaitEvent(sB, evRoot, 0);

    // Branch A — node pipeline: memset y -> scatter -> y@w0.
    cudaMemsetAsync(py, 0, (size_t)NN * 64 * sizeof(float), sA);
    k_node_scatter<<<(NE * 16 + 255) / 256, 256, 0, sA>>>((const float4*)x, en_raw);
    k_node_gemm<<<(NN + 63) / 64, 256, 0, sA>>>();
    cudaEventRecord(evA, sA);

    // Branch B — triangle pipeline: memset z1 -> tri GEMM + scatter.
    cudaMemsetAsync(pz, 0, (size_t)NE * 64 * sizeof(float), sB);
    k_tri<<<NT / 64, 256, 0, sB>>>((const float4*)x, te_raw);
    cudaEventRecord(evB, sB);

    // Join, then fused final GEMM + epilogue.
    cudaStreamWaitEvent(0, evA, 0);
    cudaStreamWaitEvent(0, evB, 0);
    k_final<<<NE / 64, 256>>>((const float4*)x, en_raw, out);
}

// round 16
// speedup vs baseline: 1.4142x; 1.0186x over previous
#include <cuda_runtime.h>
#include <cuda_bf16.h>
#include <cstdint>

#define NE 1000000
#define NN 500000
#define NT 600000

// Scratch (device globals — no cudaMalloc allowed). 16B-aligned for float4/red.v4.
__device__ __align__(16) float g_y[(size_t)NN * 64];   // node accumulator (raw y; never transformed)
__device__ __align__(16) float g_z1[(size_t)NE * 64];  // z1 accumulator
// Pre-split weights in ldmatrix-ready layout (stride 72 ushorts/row): [w_id][hi/lo]
__device__ __align__(16) unsigned short g_wsplit[3][2][64 * 72];

// Vectorized fp32 reduction (no return) — 1 L2 atomic op per 16B (sm_90+)
__device__ __forceinline__ void red_add_v4(float* a, float x, float y, float z, float w) {
    asm volatile("red.global.add.v4.f32 [%0], {%1,%2,%3,%4};"
                 :: "l"(a), "f"(x), "f"(y), "f"(z), "f"(w) : "memory");
}

// int64-vs-int32 detection on raw index buffer: int64 (values < 2^31) has all
// odd 32-bit words zero; random int32 indices make 4 zero odd-words ~(1e-6)^4.
__device__ __forceinline__ int detect64(const int* __restrict__ raw) {
    return (raw[1] == 0) & (raw[3] == 0) & (raw[5] == 0) & (raw[7] == 0);
}

// ---------------- tensor-core bf16x2-split GEMM machinery ----------------
struct __align__(16) SmemGemm {
    unsigned short Ah[64 * 72];
    unsigned short Al[64 * 72];
    unsigned short W[2][64 * 72];  // [0]=hi, [1]=lo; reused as float stage[64*68]
};

__device__ __forceinline__ unsigned int saddr(const void* p) {
    return (unsigned int)__cvta_generic_to_shared(p);
}
__device__ __forceinline__ void ldsm4(unsigned int r[4], unsigned int a) {
    asm volatile("ldmatrix.sync.aligned.m8n8.x4.shared.b16 {%0,%1,%2,%3}, [%4];"
                 : "=r"(r[0]), "=r"(r[1]), "=r"(r[2]), "=r"(r[3]) : "r"(a));
}
__device__ __forceinline__ void ldsm4t(unsigned int r[4], unsigned int a) {
    asm volatile("ldmatrix.sync.aligned.m8n8.x4.trans.shared.b16 {%0,%1,%2,%3}, [%4];"
                 : "=r"(r[0]), "=r"(r[1]), "=r"(r[2]), "=r"(r[3]) : "r"(a));
}
__device__ __forceinline__ void mma_bf16(float c[4], const unsigned int a[4],
                                         unsigned int b0, unsigned int b1) {
    asm volatile(
        "mma.sync.aligned.m16n8k16.row.col.f32.bf16.bf16.f32 "
        "{%0,%1,%2,%3}, {%4,%5,%6,%7}, {%8,%9}, {%0,%1,%2,%3};"
        : "+f"(c[0]), "+f"(c[1]), "+f"(c[2]), "+f"(c[3])
        : "r"(a[0]), "r"(a[1]), "r"(a[2]), "r"(a[3]), "r"(b0), "r"(b1));
}

// Pack an fp32 pair into bf16x2 hi + exact-residual bf16x2 lo (one cvt each).
__device__ __forceinline__ void pack_pair(float vx, float vy,
                                          unsigned short* hp, unsigned short* lp) {
    unsigned int h, l;
    asm("cvt.rn.bf16x2.f32 %0, %1, %2;" : "=r"(h) : "f"(vy), "f"(vx));
    float hx = __uint_as_float(h << 16);
    float hy = __uint_as_float(h & 0xFFFF0000u);
    asm("cvt.rn.bf16x2.f32 %0, %1, %2;" : "=r"(l) : "f"(vy - hy), "f"(vx - hx));
    *(unsigned int*)hp = h;
    *(unsigned int*)lp = l;
}

// Copy pre-split W (hi+lo, 9216B each) into shared with float4 loads.
__device__ __forceinline__ void copy_w(SmemGemm* s, int w_id, int tid) {
    const float4* sh = (const float4*)g_wsplit[w_id][0];
    const float4* sl = (const float4*)g_wsplit[w_id][1];
#pragma unroll
    for (int i = tid; i < 576; i += 256) {
        ((float4*)s->W[0])[i] = sh[i];
        ((float4*)s->W[1])[i] = sl[i];
    }
}

// One 64x64x64 split-GEMM pass accumulating into acc (no staging).
__device__ __forceinline__ void mma_pass(SmemGemm* s, int tid, float acc[4][4]) {
    int lane = tid & 31, wid = tid >> 5;
    int warp_m = (wid & 3) * 16;
    int warp_n = (wid >> 2) * 32;
    int r8 = (lane & 7) + ((lane >> 3) & 1) * 8;
    int c8 = (lane >> 4) * 8;
#pragma unroll
    for (int k0 = 0; k0 < 64; k0 += 16) {
        unsigned int ah[4], al[4], bh[2][4], bl[2][4];
        ldsm4(ah, saddr(&s->Ah[(warp_m + r8) * 72 + k0 + c8]));
        ldsm4(al, saddr(&s->Al[(warp_m + r8) * 72 + k0 + c8]));
        ldsm4t(bh[0], saddr(&s->W[0][(k0 + r8) * 72 + warp_n + c8]));
        ldsm4t(bh[1], saddr(&s->W[0][(k0 + r8) * 72 + warp_n + 16 + c8]));
        ldsm4t(bl[0], saddr(&s->W[1][(k0 + r8) * 72 + warp_n + c8]));
        ldsm4t(bl[1], saddr(&s->W[1][(k0 + r8) * 72 + warp_n + 16 + c8]));
#pragma unroll
        for (int j = 0; j < 4; j++) {
            int g = j >> 1, p = 2 * (j & 1);
            mma_bf16(acc[j], ah, bh[g][p], bh[g][p + 1]);  // hi*hi
            mma_bf16(acc[j], ah, bl[g][p], bl[g][p + 1]);  // hi*lo
            mma_bf16(acc[j], al, bh[g][p], bh[g][p + 1]);  // lo*hi
        }
    }
}

// Stage acc fragments into fp32 stage[64*68]. Caller must __syncthreads()
// before (W reuse) and after.
__device__ __forceinline__ void stage_acc(float* stage, int tid, const float acc[4][4]) {
    int lane = tid & 31, wid = tid >> 5;
    int warp_m = (wid & 3) * 16;
    int warp_n = (wid >> 2) * 32;
    int gid = lane >> 2, tig = lane & 3;
#pragma unroll
    for (int j = 0; j < 4; j++) {
        int n = warp_n + 8 * j + 2 * tig;
        *(float2*)&stage[(warp_m + gid) * 68 + n]     = make_float2(acc[j][0], acc[j][1]);
        *(float2*)&stage[(warp_m + gid + 8) * 68 + n] = make_float2(acc[j][2], acc[j][3]);
    }
}

// K_prep: split all three weights into hi/lo bf16 (ldmatrix layout), once.
__global__ void __launch_bounds__(256) k_prep(const float* __restrict__ w0,
                                              const float* __restrict__ w1,
                                              const float* __restrict__ w2) {
    int idx = blockIdx.x * 256 + threadIdx.x;  // one fp32 PAIR per thread
    if (idx >= 3 * 2048) return;
    int w_id = idx >> 11;
    int p = idx & 2047;
    int k = p >> 5, c = (p & 31) * 2;
    const float* w = (w_id == 0) ? w0 : (w_id == 1) ? w1 : w2;
    float2 v = *(const float2*)&w[k * 64 + c];
    pack_pair(v.x, v.y, &g_wsplit[w_id][0][k * 72 + c], &g_wsplit[w_id][1][k * 72 + c]);
}

// K1: scatter +-x rows into node accumulator y. 16 threads (float4 lanes) per edge.
__global__ void __launch_bounds__(256) k_node_scatter(const float4* __restrict__ x4,
                                                      const int* __restrict__ en_raw) {
    __shared__ int s64;
    if (threadIdx.x == 0) s64 = detect64(en_raw);
    __syncthreads();
    long long tid = (long long)blockIdx.x * 256 + threadIdx.x;
    if (tid >= (long long)NE * 16) return;
    int e = (int)(tid >> 4), q = (int)(tid & 15);
    float4 v = x4[(size_t)e * 16 + q];
    int t, h;
    if (s64) { t = en_raw[4 * (size_t)e];     h = en_raw[4 * (size_t)e + 2]; }
    else     { t = en_raw[2 * (size_t)e];     h = en_raw[2 * (size_t)e + 1]; }
    red_add_v4(g_y + (size_t)t * 64 + q * 4, -v.x, -v.y, -v.z, -v.w);
    red_add_v4(g_y + (size_t)h * 64 + q * 4,  v.x,  v.y,  v.z,  v.w);
}

// K3: per triangle: w = x[e0]-x[e1]+x[e2]; p = w@w2; scatter +p,-p,+p into z1.
__global__ void __launch_bounds__(256) k_tri(const float4* __restrict__ x4,
                                             const int* __restrict__ te_raw) {
    __shared__ SmemGemm s;
    __shared__ int se[192];
    __shared__ int s64;
    int tid = threadIdx.x;
    size_t t0 = (size_t)blockIdx.x * 64;
    if (tid == 0) s64 = detect64(te_raw);
    copy_w(&s, 2, tid);
    __syncthreads();
    if (tid < 192)
        se[tid] = s64 ? te_raw[2 * (t0 * 3 + tid)] : te_raw[t0 * 3 + tid];
    __syncthreads();
#pragma unroll
    for (int i = tid; i < 1024; i += 256) {
        int r = i >> 4, q = i & 15;
        int e0 = se[r * 3], e1 = se[r * 3 + 1], e2 = se[r * 3 + 2];
        float4 a = x4[(size_t)e0 * 16 + q];
        float4 b = x4[(size_t)e1 * 16 + q];
        float4 c = x4[(size_t)e2 * 16 + q];
        pack_pair(a.x - b.x + c.x, a.y - b.y + c.y,
                  &s.Ah[r * 72 + q * 4],     &s.Al[r * 72 + q * 4]);
        pack_pair(a.z - b.z + c.z, a.w - b.w + c.w,
                  &s.Ah[r * 72 + q * 4 + 2], &s.Al[r * 72 + q * 4 + 2]);
    }
    __syncthreads();
    float acc[4][4] = {};
    mma_pass(&s, tid, acc);
    __syncthreads();
    float* stage = (float*)s.W;
    stage_acc(stage, tid, acc);
    __syncthreads();
#pragma unroll
    for (int i = tid; i < 1024; i += 256) {
        int r = i >> 4, q = i & 15;
        float4 p = *(const float4*)&stage[r * 68 + q * 4];
        int e0 = se[r * 3], e1 = se[r * 3 + 1], e2 = se[r * 3 + 2];
        red_add_v4(g_z1 + (size_t)e0 * 64 + q * 4,  p.x,  p.y,  p.z,  p.w);
        red_add_v4(g_z1 + (size_t)e1 * 64 + q * 4, -p.x, -p.y, -p.z, -p.w);
        red_add_v4(g_z1 + (size_t)e2 * 64 + q * 4,  p.x,  p.y,  p.z,  p.w);
    }
}

// K4: out = tanh(x@w1 + (y[h]-y[t])@w0 + z1), two MMA passes into one acc.
__global__ void __launch_bounds__(256) k_final(const float4* __restrict__ x4,
                                               const int* __restrict__ en_raw,
                                               float* __restrict__ out) {
    __shared__ SmemGemm s;
    __shared__ int s64;
    __shared__ int sth[128];  // per-row tail/head
    int tid = threadIdx.x;
    size_t r0 = (size_t)blockIdx.x * 64;
    if (tid == 0) s64 = detect64(en_raw);
    copy_w(&s, 1, tid);  // w1 for pass 1
    __syncthreads();
    // Row indices once per row.
    if (tid < 128) {
        size_t row = r0 + (tid >> 1);
        int which = tid & 1;  // 0=tail,1=head
        sth[tid] = s64 ? en_raw[4 * row + 2 * which] : en_raw[2 * row + which];
    }
    // Fill A with x rows (pass 1).
#pragma unroll
    for (int i = tid; i < 1024; i += 256) {
        int r = i >> 4, q = i & 15;
        float4 v = x4[(r0 + r) * 16 + q];
        pack_pair(v.x, v.y, &s.Ah[r * 72 + q * 4],     &s.Al[r * 72 + q * 4]);
        pack_pair(v.z, v.w, &s.Ah[r * 72 + q * 4 + 2], &s.Al[r * 72 + q * 4 + 2]);
    }
    __syncthreads();
    float acc[4][4] = {};
    mma_pass(&s, tid, acc);  // acc = x@w1
    __syncthreads();         // A + W reads complete
    // Refill A with dy = y[head]-y[tail]; swap W to w0.
    copy_w(&s, 0, tid);
    const float4* y4 = (const float4*)g_y;
#pragma unroll
    for (int i = tid; i < 1024; i += 256) {
        int r = i >> 4, q = i & 15;
        int t = sth[2 * r], h = sth[2 * r + 1];
        float4 vh = y4[(size_t)h * 16 + q];
        float4 vt = y4[(size_t)t * 16 + q];
        pack_pair(vh.x - vt.x, vh.y - vt.y,
                  &s.Ah[r * 72 + q * 4],     &s.Al[r * 72 + q * 4]);
        pack_pair(vh.z - vt.z, vh.w - vt.w,
                  &s.Ah[r * 72 + q * 4 + 2], &s.Al[r * 72 + q * 4 + 2]);
    }
    __syncthreads();
    mma_pass(&s, tid, acc);  // acc += dy@w0
    __syncthreads();
    float* stage = (float*)s.W;
    stage_acc(stage, tid, acc);
    __syncthreads();
#pragma unroll
    for (int i = tid; i < 1024; i += 256) {
        int r = i >> 4, q = i & 15;
        size_t row = r0 + r;
        float4 g = *(const float4*)&stage[r * 68 + q * 4];
        const float4 z1v = *(const float4*)&g_z1[row * 64 + q * 4];
        float4 o;
        o.x = tanhf(g.x + z1v.x);
        o.y = tanhf(g.y + z1v.y);
        o.z = tanhf(g.z + z1v.z);
        o.w = tanhf(g.w + z1v.w);
        *(float4*)&out[row * 64 + q * 4] = o;
    }
}

extern "C" void kernel_launch(void* const* d_in, const int* in_sizes, int n_in,
                              void* d_out, int out_size) {
    // Resolve inputs by element count:
    //   x: 64,000,000  edge_nodes: 2,000,000  tri_edges: 1,800,000  w: 4,096 (x3, in order)
    const float* x = nullptr;
    const int* en_raw = nullptr;
    const int* te_raw = nullptr;
    const float* w[3] = {nullptr, nullptr, nullptr};
    int wi = 0;
    for (int i = 0; i < n_in; i++) {
        switch (in_sizes[i]) {
            case 64000000: x = (const float*)d_in[i]; break;
            case 2000000:  en_raw = (const int*)d_in[i]; break;
            case 1800000:  te_raw = (const int*)d_in[i]; break;
            case 4096:     if (wi < 3) w[wi++] = (const float*)d_in[i]; break;
            default: break;
        }
    }
    float* out = (float*)d_out;

    void *py = nullptr, *pz = nullptr;
    cudaGetSymbolAddress(&py, g_y);
    cudaGetSymbolAddress(&pz, g_z1);

    // Fork/join streams (created on first, non-captured call).
    static cudaStream_t sA = nullptr, sB = nullptr;
    static cudaEvent_t evRoot = nullptr, evA = nullptr, evB = nullptr;
    if (sA == nullptr) {
        cudaStreamCreateWithFlags(&sA, cudaStreamNonBlocking);
        cudaStreamCreateWithFlags(&sB, cudaStreamNonBlocking);
        cudaEventCreateWithFlags(&evRoot, cudaEventDisableTiming);
        cudaEventCreateWithFlags(&evA, cudaEventDisableTiming);
        cudaEventCreateWithFlags(&evB, cudaEventDisableTiming);
    }

    // Weight split prep on the root stream, then fork.
    k_prep<<<24, 256>>>(w[0], w[1], w[2]);
    cudaEventRecord(evRoot, 0);
    cudaStreamWaitEvent(sA, evRoot, 0);
    cudaStreamWaitEvent(sB, evRoot, 0);

    // Branch A — node pipeline: memset y -> scatter (raw y; used by k_final).
    cudaMemsetAsync(py, 0, (size_t)NN * 64 * sizeof(float), sA);
    k_node_scatter<<<(NE * 16 + 255) / 256, 256, 0, sA>>>((const float4*)x, en_raw);
    cudaEventRecord(evA, sA);

    // Branch B — triangle pipeline: memset z1 -> tri GEMM + scatter.
    cudaMemsetAsync(pz, 0, (size_t)NE * 64 * sizeof(float), sB);
    k_tri<<<NT / 64, 256, 0, sB>>>((const float4*)x, te_raw);
    cudaEventRecord(evB, sB);

    // Join, then fused final double-GEMM + epilogue.
    cudaStreamWaitEvent(0, evA, 0);
    cudaStreamWaitEvent(0, evB, 0);
    k_final<<<NE / 64, 256>>>((const float4*)x, en_raw, out);
}